// round 11
// baseline (speedup 1.0000x reference)
#include <cuda_runtime.h>
#include <math.h>
#include <stdint.h>

#define N_E    8192
#define E_DIM  32
#define T_TOK  32768
#define ROW_B  48             // int8 row stride: 32B data + pad (conflict-free, 16B aligned)
#define NCHUNK 256
#define CHUNKS 32
#define MCTA   64
#define GRID_MAIN 512
#define WINDOW_I 800          // ~0.05 in float units (127^2 scale); ~11 sigma of int-noise
#define CAND_CAP 16
#define PRESEED 5000          // safe floor: P(token max below) ~ e^-325

// ---- device scratch ----
__device__ float  g_en  [N_E * E_DIM];   // normalized codebook fp32 (rescore/gather)
__device__ float  g_bias[N_E];           // -0.5 * ||en||^2 (stage-B only)
__device__ char   g_Bq  [N_E * 32];      // int8 codebook rows (rn(127*e))
__device__ float  g_part[GRID_MAIN];
__device__ unsigned int g_done = 0;      // last-block counter (self-resetting)

// ---- smem layout (bytes) ----
#define A_OFF    0
#define B0_OFF   3072
#define B1_OFF   15360
#define SMEM_TOTAL 27648

#define CP_ASYNC16(s, g) asm volatile("cp.async.cg.shared.global [%0], [%1], 16;" :: "r"(s), "l"(g) : "memory")
#define CP_COMMIT()      asm volatile("cp.async.commit_group;" ::: "memory")
#define CP_WAIT1()       asm volatile("cp.async.wait_group 1;" ::: "memory")
#define CP_WAIT0()       asm volatile("cp.async.wait_group 0;" ::: "memory")

#define LDSM_X4(r0, r1, r2, r3, a)                                              \
    asm volatile("ldmatrix.sync.aligned.m8n8.x4.shared.b16 "                    \
                 "{%0,%1,%2,%3}, [%4];"                                         \
                 : "=r"(r0), "=r"(r1), "=r"(r2), "=r"(r3) : "r"(a))

__device__ __forceinline__ uint32_t smem_u32(const void* p) {
    uint32_t a;
    asm("{ .reg .u64 t; cvta.to.shared.u64 t, %1; cvt.u32.u64 %0, t; }" : "=r"(a) : "l"(p));
    return a;
}

// s8 IMMA m16n8k32: c0=(row g, col 2tig) c1=(g,2tig+1) c2=(g+8,2tig) c3=(g+8,2tig+1)
__device__ __forceinline__ void imma(int& c0, int& c1, int& c2, int& c3,
                                     uint32_t a0, uint32_t a1, uint32_t a2, uint32_t a3,
                                     uint32_t b0, uint32_t b1) {
    asm volatile("mma.sync.aligned.m16n8k32.row.col.s32.s8.s8.s32 "
                 "{%0,%1,%2,%3}, {%4,%5,%6,%7}, {%8,%9}, {%0,%1,%2,%3};"
                 : "+r"(c0), "+r"(c1), "+r"(c2), "+r"(c3)
                 : "r"(a0), "r"(a1), "r"(a2), "r"(a3), "r"(b0), "r"(b1));
}

// rare-path int top-4 insertion
#define INS4(s, n, b1, i1, b2, i2, b3, i3, b4, i4)                             \
    do { int _s = (s); int _n = (n);                                           \
         if (_s > (b4)) {                                                      \
             if (_s > (b2)) {                                                  \
                 if (_s > (b1)) { (b4)=(b3);(i4)=(i3); (b3)=(b2);(i3)=(i2);    \
                                  (b2)=(b1);(i2)=(i1); (b1)=_s;(i1)=_n; }      \
                 else { (b4)=(b3);(i4)=(i3); (b3)=(b2);(i3)=(i2); (b2)=_s;(i2)=_n; } \
             } else {                                                          \
                 if (_s > (b3)) { (b4)=(b3);(i4)=(i3); (b3)=_s;(i3)=_n; }      \
                 else { (b4)=_s;(i4)=_n; }                                     \
             }                                                                 \
         } } while (0)

// =====================================================================
// Prep: normalize codebook -> g_en (fp32), g_bias, int8 rows g_Bq
// =====================================================================
__global__ void prep_kernel(const float* __restrict__ emb) {
    int row  = blockIdx.x * 8 + (threadIdx.x >> 5);
    int lane = threadIdx.x & 31;
    float v  = emb[row * E_DIM + lane];
    float ss = v * v;
    #pragma unroll
    for (int o = 16; o; o >>= 1) ss += __shfl_xor_sync(0xFFFFFFFFu, ss, o);
    float inv = 1.0f / fmaxf(sqrtf(ss), 1e-12f);
    float e = v * inv;
    g_en[row * E_DIM + lane] = e;
    float s2 = e * e;
    #pragma unroll
    for (int o = 16; o; o >>= 1) s2 += __shfl_xor_sync(0xFFFFFFFFu, s2, o);
    if (lane == 0) g_bias[row] = -0.5f * s2;
    g_Bq[row * 32 + lane] = (char)__float2int_rn(e * 127.0f);
}

// =====================================================================
// Main: int8 IMMA coarse + batched guards (1 per 32 codes) + preseed,
// stage-B fp32 rescore, fused last-block loss finish
// =====================================================================
__device__ __forceinline__ void prefetch_chunk(int ch, uint32_t bbase, int tid) {
    #pragma unroll
    for (int h = 0; h < 2; h++) {
        int row = tid + h * 128;
        const char* src = g_Bq + (size_t)(ch * NCHUNK + row) * 32;
        uint32_t dst = bbase + row * ROW_B;
        CP_ASYNC16(dst,      src);
        CP_ASYNC16(dst + 16, src + 16);
    }
}

__global__ void __launch_bounds__(128, 4) vq_main_kernel(const float* __restrict__ z,
                                                         float* __restrict__ out) {
    extern __shared__ char smem[];
    const uint32_t sb = smem_u32(smem);
    const int tid  = threadIdx.x;
    const int lane = tid & 31;
    const int w    = tid >> 5;
    const int tok0 = blockIdx.x * MCTA;
    const int g    = lane >> 2;
    const int tig  = lane & 3;

    prefetch_chunk(0, sb + B0_OFF, tid); CP_COMMIT();
    prefetch_chunk(1, sb + B1_OFF, tid); CP_COMMIT();

    // build int8 A tile (threads 0-63): one token per thread
    if (tid < MCTA) {
        const int t = tok0 + tid;
        float x[E_DIM];
        const float4* zr = (const float4*)(z + (size_t)t * E_DIM);
        float ss = 0.0f;
        #pragma unroll
        for (int j = 0; j < 8; j++) {
            float4 v = zr[j];
            x[4*j+0] = v.x; x[4*j+1] = v.y; x[4*j+2] = v.z; x[4*j+3] = v.w;
            ss += v.x*v.x + v.y*v.y + v.z*v.z + v.w*v.w;
        }
        float inv = 1.0f / fmaxf(sqrtf(ss), 1e-12f);
        char* arow = smem + A_OFF + tid * ROW_B;
        #pragma unroll
        for (int d = 0; d < E_DIM; d++)
            arow[d] = (char)__float2int_rn(x[d] * inv * 127.0f);
    }
    __syncthreads();

    // A fragments (validated round 10)
    uint32_t af0, af1, af2, af3;
    {
        const char* ab = smem + A_OFF;
        const int r0 = w * 16 + g;
        af0 = *(const uint32_t*)(ab + r0 * ROW_B + 4 * tig);
        af1 = *(const uint32_t*)(ab + (r0 + 8) * ROW_B + 4 * tig);
        af2 = *(const uint32_t*)(ab + r0 * ROW_B + 16 + 4 * tig);
        af3 = *(const uint32_t*)(ab + (r0 + 8) * ROW_B + 16 + 4 * tig);
    }

    int b1A = PRESEED, b2A = PRESEED, b3A = PRESEED, b4A = PRESEED;
    int b1B = PRESEED, b2B = PRESEED, b3B = PRESEED, b4B = PRESEED;
    int i1A = 0, i2A = 0, i3A = 0, i4A = 0;
    int i1B = 0, i2B = 0, i3B = 0, i4B = 0;
    int b4min = PRESEED;

    // ldmatrix address map (validated round 10)
    const uint32_t lmo = (uint32_t)(lane & 7) * ROW_B
                       + (uint32_t)((lane >> 3) & 1) * 16
                       + (uint32_t)(lane >> 4) * (8 * ROW_B);

    for (int ch = 0; ch < CHUNKS; ch++) {
        CP_WAIT1();
        __syncthreads();
        const uint32_t bbase = sb + ((ch & 1) ? B1_OFF : B0_OFF);
        const int nbase = ch * NCHUNK;

        #pragma unroll 2
        for (int np2 = 0; np2 < 8; np2++) {          // 32 codes per iteration
            uint32_t q0, q1, q2, q3, p0, p1, p2, p3;
            uint32_t a0 = bbase + (uint32_t)np2 * (32 * ROW_B) + lmo;
            LDSM_X4(q0, q1, q2, q3, a0);
            LDSM_X4(p0, p1, p2, p3, a0 + 16 * ROW_B);
            int c0 = 0, c1 = 0, c2 = 0, c3 = 0;
            int d0 = 0, d1 = 0, d2 = 0, d3 = 0;
            int e0 = 0, e1 = 0, e2 = 0, e3 = 0;
            int f0 = 0, f1 = 0, f2 = 0, f3 = 0;
            imma(c0, c1, c2, c3, af0, af1, af2, af3, q0, q1);   // codes +0..7
            imma(d0, d1, d2, d3, af0, af1, af2, af3, q2, q3);   // codes +8..15
            imma(e0, e1, e2, e3, af0, af1, af2, af3, p0, p1);   // codes +16..23
            imma(f0, f1, f2, f3, af0, af1, af2, af3, p2, p3);   // codes +24..31

            int mA = max(max(max(c0, c1), max(d0, d1)), max(max(e0, e1), max(f0, f1)));
            int mB = max(max(max(c2, c3), max(d2, d3)), max(max(e2, e3), max(f2, f3)));
            if (max(mA, mB) > b4min) {               // single rare guard per 32 codes
                const int nb0 = nbase + np2 * 32 + 2 * tig;
                if (mA > b4A) {
                    INS4(c0, nb0,      b1A, i1A, b2A, i2A, b3A, i3A, b4A, i4A);
                    INS4(c1, nb0 + 1,  b1A, i1A, b2A, i2A, b3A, i3A, b4A, i4A);
                    INS4(d0, nb0 + 8,  b1A, i1A, b2A, i2A, b3A, i3A, b4A, i4A);
                    INS4(d1, nb0 + 9,  b1A, i1A, b2A, i2A, b3A, i3A, b4A, i4A);
                    INS4(e0, nb0 + 16, b1A, i1A, b2A, i2A, b3A, i3A, b4A, i4A);
                    INS4(e1, nb0 + 17, b1A, i1A, b2A, i2A, b3A, i3A, b4A, i4A);
                    INS4(f0, nb0 + 24, b1A, i1A, b2A, i2A, b3A, i3A, b4A, i4A);
                    INS4(f1, nb0 + 25, b1A, i1A, b2A, i2A, b3A, i3A, b4A, i4A);
                }
                if (mB > b4B) {
                    INS4(c2, nb0,      b1B, i1B, b2B, i2B, b3B, i3B, b4B, i4B);
                    INS4(c3, nb0 + 1,  b1B, i1B, b2B, i2B, b3B, i3B, b4B, i4B);
                    INS4(d2, nb0 + 8,  b1B, i1B, b2B, i2B, b3B, i3B, b4B, i4B);
                    INS4(d3, nb0 + 9,  b1B, i1B, b2B, i2B, b3B, i3B, b4B, i4B);
                    INS4(e2, nb0 + 16, b1B, i1B, b2B, i2B, b3B, i3B, b4B, i4B);
                    INS4(e3, nb0 + 17, b1B, i1B, b2B, i2B, b3B, i3B, b4B, i4B);
                    INS4(f2, nb0 + 24, b1B, i1B, b2B, i2B, b3B, i3B, b4B, i4B);
                    INS4(f3, nb0 + 25, b1B, i1B, b2B, i2B, b3B, i3B, b4B, i4B);
                }
                b4min = min(b4A, b4B);
            }
        }
        __syncthreads();
        if (ch + 2 < CHUNKS) prefetch_chunk(ch + 2, bbase, tid);
        CP_COMMIT();
    }
    CP_WAIT0();
    __syncthreads();

    // ---- candidate collection (reuse B0 region) ----
    int* s_cnt  = (int*)(smem + B0_OFF);
    int* s_list = (int*)(smem + B0_OFF + 256);
    if (tid < MCTA) s_cnt[tid] = 0;
    __syncthreads();

    int mA = b1A, mB = b1B;
    #pragma unroll
    for (int o = 1; o <= 2; o <<= 1) {
        mA = max(mA, __shfl_xor_sync(0xFFFFFFFFu, mA, o));
        mB = max(mB, __shfl_xor_sync(0xFFFFFFFFu, mB, o));
    }
    const int tokA = w * 16 + g;
    const int tokB = tokA + 8;
    int thrA = mA - WINDOW_I, thrB = mB - WINDOW_I;
    if (b1A >= thrA) { int p = atomicAdd(&s_cnt[tokA], 1); if (p < CAND_CAP) s_list[tokA * CAND_CAP + p] = i1A; }
    if (b2A >= thrA) { int p = atomicAdd(&s_cnt[tokA], 1); if (p < CAND_CAP) s_list[tokA * CAND_CAP + p] = i2A; }
    if (b3A >= thrA) { int p = atomicAdd(&s_cnt[tokA], 1); if (p < CAND_CAP) s_list[tokA * CAND_CAP + p] = i3A; }
    if (b4A >= thrA) { int p = atomicAdd(&s_cnt[tokA], 1); if (p < CAND_CAP) s_list[tokA * CAND_CAP + p] = i4A; }
    if (b1B >= thrB) { int p = atomicAdd(&s_cnt[tokB], 1); if (p < CAND_CAP) s_list[tokB * CAND_CAP + p] = i1B; }
    if (b2B >= thrB) { int p = atomicAdd(&s_cnt[tokB], 1); if (p < CAND_CAP) s_list[tokB * CAND_CAP + p] = i2B; }
    if (b3B >= thrB) { int p = atomicAdd(&s_cnt[tokB], 1); if (p < CAND_CAP) s_list[tokB * CAND_CAP + p] = i3B; }
    if (b4B >= thrB) { int p = atomicAdd(&s_cnt[tokB], 1); if (p < CAND_CAP) s_list[tokB * CAND_CAP + p] = i4B; }
    __syncthreads();

    // ---- stage B: fp32 rescore + outputs + loss (validated path) ----
    float lsum = 0.0f;
    if (tid < MCTA) {
        const int t = tok0 + tid;
        float zn[E_DIM];
        const float4* zr = (const float4*)(z + (size_t)t * E_DIM);
        float ss = 0.0f;
        #pragma unroll
        for (int j = 0; j < 8; j++) {
            float4 v = zr[j];
            zn[4*j+0] = v.x; zn[4*j+1] = v.y; zn[4*j+2] = v.z; zn[4*j+3] = v.w;
            ss += v.x*v.x + v.y*v.y + v.z*v.z + v.w*v.w;
        }
        float inv = 1.0f / fmaxf(sqrtf(ss), 1e-12f);
        #pragma unroll
        for (int d = 0; d < E_DIM; d++) zn[d] *= inv;

        int nc = s_cnt[tid]; if (nc > CAND_CAP) nc = CAND_CAP;
        float best = -3.4e38f;
        int   bi   = 0x7FFFFFFF;
        for (int j = 0; j < nc; j++) {
            int ci = s_list[tid * CAND_CAP + j];
            const float* er = g_en + (size_t)ci * E_DIM;
            float dot = 0.0f;
            #pragma unroll
            for (int d = 0; d < E_DIM; d++) dot = fmaf(zn[d], er[d], dot);
            float s = dot + g_bias[ci];
            if (s > best || (s == best && ci < bi)) { best = s; bi = ci; }
        }

        float o[E_DIM];
        const float* eq = g_en + (size_t)bi * E_DIM;
        #pragma unroll
        for (int d = 0; d < E_DIM; d++) {
            float df = eq[d] - zn[d];
            lsum += df * df;
            o[d] = zn[d] + df;
        }
        float4* orow = (float4*)(out + (size_t)t * E_DIM);
        #pragma unroll
        for (int j = 0; j < 8; j++)
            orow[j] = make_float4(o[4*j], o[4*j+1], o[4*j+2], o[4*j+3]);
        out[(size_t)T_TOK * E_DIM + 1 + t] = (float)bi;
    }

    __syncthreads();
    float* s_red = (float*)smem;
    s_red[tid] = lsum;
    __syncthreads();
    #pragma unroll
    for (int k = 64; k; k >>= 1) {
        if (tid < k) s_red[tid] += s_red[tid + k];
        __syncthreads();
    }
    __shared__ unsigned int s_last;
    if (tid == 0) {
        g_part[blockIdx.x] = s_red[0];
        __threadfence();
        s_last = atomicAdd(&g_done, 1u);
    }
    __syncthreads();

    // last block: deterministic final loss reduction, then reset counter
    if (s_last == GRID_MAIN - 1) {
        float v = 0.0f;
        #pragma unroll
        for (int j = 0; j < 4; j++) v += g_part[tid + j * 128];
        s_red[tid] = v;
        __syncthreads();
        #pragma unroll
        for (int k = 64; k; k >>= 1) {
            if (tid < k) s_red[tid] += s_red[tid + k];
            __syncthreads();
        }
        if (tid == 0) {
            out[(size_t)T_TOK * E_DIM] = 1.25f * s_red[0] / (float)(T_TOK * E_DIM);
            g_done = 0;                 // reset for next graph replay
        }
    }
}

extern "C" void kernel_launch(void* const* d_in, const int* in_sizes, int n_in,
                              void* d_out, int out_size) {
    const float* z   = (const float*)d_in[0];
    const float* emb = (const float*)d_in[1];
    float* out = (float*)d_out;

    cudaFuncSetAttribute(vq_main_kernel, cudaFuncAttributeMaxDynamicSharedMemorySize, SMEM_TOTAL);

    prep_kernel<<<N_E / 8, 256>>>(emb);
    vq_main_kernel<<<GRID_MAIN, 128, SMEM_TOTAL>>>(z, out);
}